// round 7
// baseline (speedup 1.0000x reference)
#include <cuda_runtime.h>

// ButterflyTransform: x[8192,4096] fp32, W[12,2048,2,2] fp32.
// All 12 layers pair adjacent elements identically -> per pair n the network
// collapses to one composed 2x2 matrix M[n] = W0[n]@...@W11[n]  (y = x*W).
//
// SINGLE kernel (two graph nodes cost ~8us of pure launch gap, measured):
//   - blocks 0..7 compose the 2048 matrices into g_M (384 KB of W reads, once)
//   - all blocks acquire-spin on g_done, then run the proven R1 streaming body
//   - last finishing block resets the flags so graph replays start clean

#define BATCH   8192
#define SIZE    4096
#define NPAIRS  (SIZE / 2)        // 2048
#define LOG_N   12
#define F4_PER_ROW (SIZE / 4)     // 1024 float4 per row

#define TPB     256
#define ROWS_PER_BLOCK 16
#define GRID_X  (F4_PER_ROW / TPB)        // 4 strips
#define GRID_Y  (BATCH / ROWS_PER_BLOCK)  // 512
#define TOTAL_BLOCKS (GRID_X * GRID_Y)    // 2048
#define NCOMPOSE 8                        // composer blocks (flat id 0..7)

__device__ float4 g_M[NPAIRS];   // composed matrices (32 KB)
__device__ int    g_done;        // composer completion count (0..NCOMPOSE)
__device__ int    g_fin;         // finished-block count (for flag reset)

__device__ __forceinline__ float4 mm2x2(float4 m, float4 w) {
    // row-vector composition: (m @ w)
    float4 t;
    t.x = fmaf(m.x, w.x, m.y * w.z);
    t.y = fmaf(m.x, w.y, m.y * w.w);
    t.z = fmaf(m.z, w.x, m.w * w.z);
    t.w = fmaf(m.z, w.y, m.w * w.w);
    return t;
}

__global__ void __launch_bounds__(TPB)
fused_kernel(const float* __restrict__ x,
             const float* __restrict__ W,
             float* __restrict__ out) {
    const int tid  = threadIdx.x;
    const int flat = blockIdx.y * gridDim.x + blockIdx.x;

    // ---- phase 1: blocks 0..7 compose all 2048 matrices (1 pair/thread) ----
    if (flat < NCOMPOSE) {
        const int n = flat * TPB + tid;                    // pair index
        const float4* __restrict__ Wp = reinterpret_cast<const float4*>(W) + n;
        float4 m;
        {   // group-of-4 load hoisting: bounded regs, 3 latency exposures
            float4 w0 = Wp[0 * NPAIRS], w1 = Wp[1 * NPAIRS];
            float4 w2 = Wp[2 * NPAIRS], w3 = Wp[3 * NPAIRS];
            m = mm2x2(mm2x2(mm2x2(w0, w1), w2), w3);
        }
#pragma unroll
        for (int g = 1; g < LOG_N / 4; g++) {
            float4 w0 = Wp[(4 * g + 0) * NPAIRS], w1 = Wp[(4 * g + 1) * NPAIRS];
            float4 w2 = Wp[(4 * g + 2) * NPAIRS], w3 = Wp[(4 * g + 3) * NPAIRS];
            m = mm2x2(mm2x2(mm2x2(mm2x2(m, w0), w1), w2), w3);
        }
        g_M[n] = m;
        __threadfence();           // publish g_M before the flag
        __syncthreads();           // whole block's stores are fenced
        if (tid == 0) atomicAdd(&g_done, 1);
    }

    // ---- wait for compose to be published (1 poller/block) ----
    if (tid == 0) {
        int v;
        for (;;) {
            asm volatile("ld.acquire.gpu.global.b32 %0, [%1];"
                         : "=r"(v) : "l"(&g_done) : "memory");
            if (v >= NCOMPOSE) break;
            __nanosleep(64);
        }
    }
    __syncthreads();               // acquire by t0 + barrier orders g_M reads

    // ---- phase 2: streaming apply (exact R1 body: 37.1us @ 73% DRAM) ----
    const int col4 = blockIdx.x * TPB + tid;          // 0..1023
    const float4 mA = g_M[2 * col4];
    const float4 mB = g_M[2 * col4 + 1];

    const float4* __restrict__ xin  = reinterpret_cast<const float4*>(x);
    float4* __restrict__       yout = reinterpret_cast<float4*>(out);

    long base = (long)blockIdx.y * ROWS_PER_BLOCK * F4_PER_ROW + col4;
#pragma unroll
    for (int r = 0; r < ROWS_PER_BLOCK; r++) {
        long idx = base + (long)r * F4_PER_ROW;
        float4 v = xin[idx];
        float4 o;
        o.x = fmaf(v.x, mA.x, v.y * mA.z);
        o.y = fmaf(v.x, mA.y, v.y * mA.w);
        o.z = fmaf(v.z, mB.x, v.w * mB.z);
        o.w = fmaf(v.z, mB.y, v.w * mB.w);
        yout[idx] = o;
    }

    // ---- epilogue: last block resets flags so graph replays start clean ----
    if (tid == 0) {
        __threadfence();
        int f = atomicAdd(&g_fin, 1);
        if (f == TOTAL_BLOCKS - 1) {
            g_done = 0;
            g_fin  = 0;
            __threadfence();
        }
    }
}

extern "C" void kernel_launch(void* const* d_in, const int* in_sizes, int n_in,
                              void* d_out, int out_size) {
    const float* x = (const float*)d_in[0];   // [8192, 4096]
    const float* W = (const float*)d_in[1];   // [12, 2048, 2, 2]
    float* out = (float*)d_out;

    dim3 grid(GRID_X, GRID_Y);                // (4, 512)
    fused_kernel<<<grid, TPB>>>(x, W, out);
}